// round 9
// baseline (speedup 1.0000x reference)
#include <cuda_runtime.h>
#include <math.h>

#define B_  64
#define N_  2048
#define K_  128
#define J_  10
#define D_  16
#define F_  160   // J_*D_

typedef unsigned long long u64;

// scratch (device globals: no allocation allowed)
__device__ float g_s [B_*K_];        // sum over n of u
__device__ float g_v [B_*J_*K_];     // v[b,j,k] = sum_d W[k,jd]*o[b,j,d]
__device__ float g_p1[B_*J_*K_];     // p after routing iter 1
__device__ float g_p2[B_*J_*K_];     // p after routing iter 2

__device__ __forceinline__ u64 ffma2(u64 a, u64 b, u64 c) {
    u64 d; asm("fma.rn.f32x2 %0, %1, %2, %3;" : "=l"(d) : "l"(a), "l"(b), "l"(c));
    return d;
}
__device__ __forceinline__ u64 pack2(float x, float y) {
    u64 d; asm("mov.b64 %0, {%1, %2};" : "=l"(d) : "f"(x), "f"(y));
    return d;
}
__device__ __forceinline__ float2 unpack2(u64 v) {
    float2 r; asm("mov.b64 {%0, %1}, %2;" : "=f"(r.x), "=f"(r.y) : "l"(v));
    return r;
}

// s[b,k] = sum_n u[b,n,k] — one block per b, direct store (no init, no atomics)
__global__ void k_sum(const float* __restrict__ u) {
    int b = blockIdx.x;
    int k4 = threadIdx.x & 31;
    int rg = threadIdx.x >> 5;         // 8 row groups of 256 rows
    const float4* up = (const float4*)(u + ((size_t)b*N_ + (size_t)rg*256)*K_);
    float4 acc = make_float4(0.f,0.f,0.f,0.f);
#pragma unroll 8
    for (int r = 0; r < 256; r++) {
        float4 t = up[r*32 + k4];
        acc.x += t.x; acc.y += t.y; acc.z += t.z; acc.w += t.w;
    }
    __shared__ float4 sred[8][32];
    sred[rg][k4] = acc;
    __syncthreads();
    if (rg == 0) {
#pragma unroll
        for (int i = 1; i < 8; i++) {
            float4 t = sred[i][k4];
            acc.x += t.x; acc.y += t.y; acc.z += t.z; acc.w += t.w;
        }
        ((float4*)(g_s + b*K_))[k4] = acc;
    }
}

// mode 0: o[b,j,d] = 0.1 * sum_k s[b,k]   * W[k, j*16+d]   ; zeros g_p1[b]
// mode 1: o[b,j,d] =       sum_k p1[b,j,k]* W[k, j*16+d]   ; zeros g_p2[b]
// then    v[b,j,k] = sum_d o[b,j,d] * W[k, j*16+d]
__global__ void k_ov(const float* __restrict__ W, int mode) {
    int b = blockIdx.x, t = threadIdx.x;   // 320 threads
    __shared__ float src[J_*K_];
    __shared__ float so[F_];
    if (mode == 0) {
        if (t < K_) src[t] = g_s[b*K_ + t];
    } else {
        for (int i = t; i < J_*K_; i += 320) src[i] = g_p1[b*J_*K_ + i];
    }
    // zero the p buffer this pass will accumulate into
    {
        float* pz = (mode == 0 ? g_p1 : g_p2) + b*J_*K_;
        for (int i = t; i < J_*K_; i += 320) pz[i] = 0.f;
    }
    __syncthreads();
    if (t < F_) {
        int j = t >> 4;
        float acc = 0.f;
        const float* wcol = W + t;
        if (mode == 0) {
#pragma unroll 8
            for (int k = 0; k < K_; k++) acc += src[k] * wcol[k*F_];
            acc *= 0.1f;
        } else {
            const float* pj = src + j*K_;
#pragma unroll 8
            for (int k = 0; k < K_; k++) acc += pj[k] * wcol[k*F_];
        }
        so[t] = acc;
    }
    __syncthreads();
    for (int e = t; e < J_*K_; e += 320) {
        int jj = e >> 7, k = e & 127;
        const float* wrow = W + k*F_ + jj*D_;
        const float* oj = so + jj*D_;
        float v = 0.f;
#pragma unroll
        for (int d2 = 0; d2 < D_; d2++) v += oj[d2] * wrow[d2];
        g_v[b*J_*K_ + e] = v;
    }
}

// fused pass: dots -> softmax -> p accumulation, 4 rows per warp-iteration.
// Lane owns k = 4*lane..4*lane+3; quarter q = lane>>3; slot r = row r0+(q^r).
// v now lives in SMEM (conflict-free LDS.128 per j) -> 40 fewer registers ->
// 3 blocks/SM (24 warps) for latency hiding. Everything else as R8.
__global__ void __launch_bounds__(256, 3)
k_pass(const float* __restrict__ u, int which) {
    float* p = (which == 0) ? g_p1 : g_p2;
    int b = blockIdx.x >> 3;
    int seg = blockIdx.x & 7;              // 256 rows per block
    int tid = threadIdx.x;
    int warp = tid >> 5, lane = tid & 31;
    int q = lane >> 3;

    __shared__ float sv[J_*K_];
    __shared__ float ps[J_*K_];
    {
        const float* vb = g_v + b*J_*K_;
        for (int i = tid; i < J_*K_; i += 256) { sv[i] = vb[i]; ps[i] = 0.f; }
    }
    __syncthreads();

    u64 p20[J_], p21[J_];
#pragma unroll
    for (int j = 0; j < J_; j++) { p20[j] = 0ULL; p21[j] = 0ULL; }

    const float4* ub = (const float4*)(u + ((size_t)b*N_ + (size_t)seg*256)*K_);
    const float4* svl = ((const float4*)sv) + lane;   // sv[j*K_ + 4*lane]

#pragma unroll 1
    for (int it = 0; it < 8; it++) {
        int r0 = warp*32 + it*4;
        // q-relative row loads: slot r holds row r0 + (q^r) at this lane's k
        u64 a0[4], a1[4];
#pragma unroll
        for (int r = 0; r < 4; r++) {
            float4 t = ub[(r0 + (q ^ r))*32 + lane];
            a0[r] = pack2(t.x, t.y);
            a1[r] = pack2(t.z, t.w);
        }

        // dots + select-free split reduction
        float pd[J_];
#pragma unroll
        for (int j = 0; j < J_; j++) {
            float4 vv = svl[j*32];         // conflict-free LDS.128
            u64 v0 = pack2(vv.x, vv.y);
            u64 v1 = pack2(vv.z, vv.w);
            float s0, s1, s2, s3;
            {
                u64 acc = ffma2(a0[0], v0, ffma2(a1[0], v1, 0ULL));
                float2 f = unpack2(acc); s0 = f.x + f.y;
            }
            {
                u64 acc = ffma2(a0[1], v0, ffma2(a1[1], v1, 0ULL));
                float2 f = unpack2(acc); s1 = f.x + f.y;
            }
            {
                u64 acc = ffma2(a0[2], v0, ffma2(a1[2], v1, 0ULL));
                float2 f = unpack2(acc); s2 = f.x + f.y;
            }
            {
                u64 acc = ffma2(a0[3], v0, ffma2(a1[3], v1, 0ULL));
                float2 f = unpack2(acc); s3 = f.x + f.y;
            }
            s0 += __shfl_xor_sync(0xffffffffu, s2, 16);
            s1 += __shfl_xor_sync(0xffffffffu, s3, 16);
            s0 += __shfl_xor_sync(0xffffffffu, s1, 8);
            s0 += __shfl_xor_sync(0xffffffffu, s0, 4);
            s0 += __shfl_xor_sync(0xffffffffu, s0, 2);
            s0 += __shfl_xor_sync(0xffffffffu, s0, 1);
            pd[j] = s0;                     // full dot of row r0+q
        }
        // softmax over j for row r0+q (once per 4 rows; per-quarter data)
        float m01 = fmaxf(pd[0], pd[1]), m23 = fmaxf(pd[2], pd[3]);
        float m45 = fmaxf(pd[4], pd[5]), m67 = fmaxf(pd[6], pd[7]);
        float m89 = fmaxf(pd[8], pd[9]);
        float mx = fmaxf(fmaxf(fmaxf(m01, m23), fmaxf(m45, m67)), m89);
        float Z = 0.f;
#pragma unroll
        for (int j = 0; j < J_; j++) { pd[j] = __expf(pd[j] - mx); Z += pd[j]; }
        float rZ = __fdividef(1.0f, Z);
        // accumulate: coefficient for slot r = shfl_xor(c_own, 8r)
#pragma unroll
        for (int j = 0; j < J_; j++) {
            float c0 = pd[j] * rZ;                            // row q
            float c1 = __shfl_xor_sync(0xffffffffu, c0, 8);   // row q^1
            float c2 = __shfl_xor_sync(0xffffffffu, c0, 16);  // row q^2
            float c3 = __shfl_xor_sync(0xffffffffu, c0, 24);  // row q^3
            u64 cc;
            cc = pack2(c0, c0);
            p20[j] = ffma2(cc, a0[0], p20[j]);
            p21[j] = ffma2(cc, a1[0], p21[j]);
            cc = pack2(c1, c1);
            p20[j] = ffma2(cc, a0[1], p20[j]);
            p21[j] = ffma2(cc, a1[1], p21[j]);
            cc = pack2(c2, c2);
            p20[j] = ffma2(cc, a0[2], p20[j]);
            p21[j] = ffma2(cc, a1[2], p21[j]);
            cc = pack2(c3, c3);
            p20[j] = ffma2(cc, a0[3], p20[j]);
            p21[j] = ffma2(cc, a1[3], p21[j]);
        }
    }

    // aggregate the 8 warps via smem, then 1 coalesced gmem atomic pass
#pragma unroll
    for (int j = 0; j < J_; j++) {
        float2 a = unpack2(p20[j]);
        float2 c = unpack2(p21[j]);
        float* d = ps + j*K_ + lane*4;
        atomicAdd(d+0, a.x); atomicAdd(d+1, a.y);
        atomicAdd(d+2, c.x); atomicAdd(d+3, c.y);
    }
    __syncthreads();
    float* pb = p + b*J_*K_;
    for (int i = tid; i < J_*K_; i += 256)
        atomicAdd(pb + i, ps[i]);
}

// o2[b,j,d] = sum_k p2[b,j,k]*W[k,jd]; out = squash(o2) over d
__global__ void k_final(const float* __restrict__ W, float* __restrict__ out) {
    int b = blockIdx.x, t = threadIdx.x;   // 160 threads
    int j = t >> 4;
    __shared__ float so[F_];
    const float* pj = g_p2 + b*J_*K_ + j*K_;
    const float* wcol = W + t;
    float acc = 0.f;
#pragma unroll 8
    for (int k = 0; k < K_; k++) acc += pj[k] * wcol[k*F_];
    so[t] = acc;
    __syncthreads();
    float s2 = 0.f;
#pragma unroll
    for (int d2 = 0; d2 < D_; d2++) { float x = so[j*D_ + d2]; s2 += x*x; }
    out[b*F_ + t] = acc * s2 / ((1.f + s2) * sqrtf(s2 + 1e-7f));
}

extern "C" void kernel_launch(void* const* d_in, const int* in_sizes, int n_in,
                              void* d_out, int out_size) {
    const float* u = (const float*)d_in[0];
    const float* W = (const float*)d_in[1];
    float* out = (float*)d_out;

    k_sum<<<B_, 256>>>(u);
    k_ov<<<B_, 320>>>(W, 0);         // o0 (c uniform), v1; zero p1
    k_pass<<<512, 256>>>(u, 0);      // b1 -> softmax -> p1
    k_ov<<<B_, 320>>>(W, 1);         // o1, v2; zero p2
    k_pass<<<512, 256>>>(u, 1);      // b2 -> softmax -> p2
    k_final<<<B_, F_>>>(W, out);     // o2 -> squash
}

// round 10
// speedup vs baseline: 1.2455x; 1.2455x over previous
#include <cuda_runtime.h>
#include <math.h>

#define B_  64
#define N_  2048
#define K_  128
#define J_  10
#define D_  16
#define F_  160   // J_*D_

typedef unsigned long long u64;

// scratch (device globals: no allocation allowed)
__device__ float g_s [B_*K_];        // sum over n of u
__device__ float g_wt[F_*K_];        // W transposed: wt[f*128 + k] = W[k*160 + f]
__device__ float g_v [B_*J_*K_];     // v[b,j,k] = sum_d W[k,jd]*o[b,j,d]
__device__ float g_p1[B_*J_*K_];     // p after routing iter 1
__device__ float g_p2[B_*J_*K_];     // p after routing iter 2

__device__ __forceinline__ u64 ffma2(u64 a, u64 b, u64 c) {
    u64 d; asm("fma.rn.f32x2 %0, %1, %2, %3;" : "=l"(d) : "l"(a), "l"(b), "l"(c));
    return d;
}
__device__ __forceinline__ u64 pack2(float x, float y) {
    u64 d; asm("mov.b64 %0, {%1, %2};" : "=l"(d) : "f"(x), "f"(y));
    return d;
}
__device__ __forceinline__ float2 unpack2(u64 v) {
    float2 r; asm("mov.b64 {%0, %1}, %2;" : "=f"(r.x), "=f"(r.y) : "l"(v));
    return r;
}

// prep: zero scratch + transpose W (grid 320 x 256)
__global__ void k_prep(const float* __restrict__ W) {
    int i = blockIdx.x * blockDim.x + threadIdx.x;
    if (i < B_*K_) g_s[i] = 0.f;
    if (i < B_*J_*K_) { g_p1[i] = 0.f; g_p2[i] = 0.f; }
    if (i < F_*K_) {
        int f = i >> 7, k = i & 127;
        g_wt[i] = W[k*F_ + f];
    }
}

// s[b,k] = sum_n u[b,n,k]  (512 blocks; smem pre-reduce; 1 atomic per k per block)
__global__ void k_sum(const float* __restrict__ u) {
    int b = blockIdx.y;
    int chunk = blockIdx.x;            // 0..7, 256 rows each
    int k4 = threadIdx.x & 31;
    int rg = threadIdx.x >> 5;
    const float4* up = (const float4*)(u + ((size_t)b*N_ + (size_t)chunk*256 + (size_t)rg*32)*K_);
    float4 acc = make_float4(0.f,0.f,0.f,0.f);
#pragma unroll 8
    for (int r = 0; r < 32; r++) {
        float4 t = up[r*32 + k4];
        acc.x += t.x; acc.y += t.y; acc.z += t.z; acc.w += t.w;
    }
    __shared__ float4 sred[8][32];
    sred[rg][k4] = acc;
    __syncthreads();
    if (rg == 0) {
#pragma unroll
        for (int i = 1; i < 8; i++) {
            float4 t = sred[i][k4];
            acc.x += t.x; acc.y += t.y; acc.z += t.z; acc.w += t.w;
        }
        float* sp = g_s + b*K_ + k4*4;
        atomicAdd(sp+0, acc.x); atomicAdd(sp+1, acc.y);
        atomicAdd(sp+2, acc.z); atomicAdd(sp+3, acc.w);
    }
}

// mode 0: o[b,j,d] = 0.1 * sum_k s[b,k]   * W[k, j*16+d]
// mode 1: o[b,j,d] =       sum_k p1[b,j,k]* W[k, j*16+d]
// then    v[b,j,k] = sum_d o[b,j,d] * W[k, j*16+d]
// Phase A: one warp per output column f, coalesced LDG.128 from g_wt,
// 5-shfl butterfly -> latency-tolerant (20 f per warp, all independent).
__global__ void k_ov(const float* __restrict__ W, int mode) {
    int b = blockIdx.x, t = threadIdx.x;   // 256 threads, 8 warps
    int warp = t >> 5, lane = t & 31;
    __shared__ float src[J_*K_];
    __shared__ float so[F_];
    if (mode == 0) {
        if (t < K_) src[t] = g_s[b*K_ + t];
    } else {
        for (int i = t; i < J_*K_; i += 256) src[i] = g_p1[b*J_*K_ + i];
    }
    __syncthreads();

    // phase A: warp w computes f = w, w+8, ..., w+152
#pragma unroll
    for (int fi = 0; fi < 20; fi++) {
        int f = warp + fi*8;
        float4 w4 = ((const float4*)(g_wt + f*K_))[lane];
        const float* sp = (mode == 0) ? src : (src + (f >> 4)*K_);
        float4 s4 = ((const float4*)sp)[lane];
        u64 acc = ffma2(pack2(w4.x, w4.y), pack2(s4.x, s4.y),
                  ffma2(pack2(w4.z, w4.w), pack2(s4.z, s4.w), 0ULL));
        float2 fr = unpack2(acc);
        float d = fr.x + fr.y;
#pragma unroll
        for (int m = 16; m >= 1; m >>= 1)
            d += __shfl_xor_sync(0xffffffffu, d, m);
        if (lane == 0) so[f] = (mode == 0) ? 0.1f * d : d;
    }
    __syncthreads();

    // phase B: v[j,k] = sum_d o[j,d] * W[k, j*16+d]
#pragma unroll
    for (int e = t; e < J_*K_; e += 256) {
        int jj = e >> 7, k = e & 127;
        const float4* wrow = (const float4*)(W + k*F_ + jj*D_);
        const float4* oj = (const float4*)(so + jj*D_);
        float4 w0 = wrow[0], w1 = wrow[1], w2 = wrow[2], w3 = wrow[3];
        float4 o0 = oj[0], o1 = oj[1], o2 = oj[2], o3 = oj[3];
        float v = w0.x*o0.x + w0.y*o0.y + w0.z*o0.z + w0.w*o0.w
                + w1.x*o1.x + w1.y*o1.y + w1.z*o1.z + w1.w*o1.w
                + w2.x*o2.x + w2.y*o2.y + w2.z*o2.z + w2.w*o2.w
                + w3.x*o3.x + w3.y*o3.y + w3.z*o3.z + w3.w*o3.w;
        g_v[b*J_*K_ + e] = v;
    }
}

// fused pass: dots -> softmax -> p accumulation, 4 rows per warp-iteration.
// Lane owns k = 4*lane..4*lane+3; quarter q = lane>>3; slot r = row r0+(q^r).
// v in SMEM (conflict-free LDS.128 per j) -> low regs -> 3 blocks/SM.
__global__ void __launch_bounds__(256, 3)
k_pass(const float* __restrict__ u, int which) {
    float* p = (which == 0) ? g_p1 : g_p2;
    int b = blockIdx.x >> 3;
    int seg = blockIdx.x & 7;              // 256 rows per block
    int tid = threadIdx.x;
    int warp = tid >> 5, lane = tid & 31;
    int q = lane >> 3;

    __shared__ float sv[J_*K_];
    __shared__ float ps[J_*K_];
    {
        const float* vb = g_v + b*J_*K_;
        for (int i = tid; i < J_*K_; i += 256) { sv[i] = vb[i]; ps[i] = 0.f; }
    }
    __syncthreads();

    u64 p20[J_], p21[J_];
#pragma unroll
    for (int j = 0; j < J_; j++) { p20[j] = 0ULL; p21[j] = 0ULL; }

    const float4* ub = (const float4*)(u + ((size_t)b*N_ + (size_t)seg*256)*K_);
    const float4* svl = ((const float4*)sv) + lane;   // sv[j*K_ + 4*lane]

#pragma unroll 1
    for (int it = 0; it < 8; it++) {
        int r0 = warp*32 + it*4;
        // q-relative row loads: slot r holds row r0 + (q^r) at this lane's k
        u64 a0[4], a1[4];
#pragma unroll
        for (int r = 0; r < 4; r++) {
            float4 t = ub[(r0 + (q ^ r))*32 + lane];
            a0[r] = pack2(t.x, t.y);
            a1[r] = pack2(t.z, t.w);
        }

        // dots + select-free split reduction
        float pd[J_];
#pragma unroll
        for (int j = 0; j < J_; j++) {
            float4 vv = svl[j*32];         // conflict-free LDS.128
            u64 v0 = pack2(vv.x, vv.y);
            u64 v1 = pack2(vv.z, vv.w);
            float s0, s1, s2, s3;
            {
                u64 acc = ffma2(a0[0], v0, ffma2(a1[0], v1, 0ULL));
                float2 f = unpack2(acc); s0 = f.x + f.y;
            }
            {
                u64 acc = ffma2(a0[1], v0, ffma2(a1[1], v1, 0ULL));
                float2 f = unpack2(acc); s1 = f.x + f.y;
            }
            {
                u64 acc = ffma2(a0[2], v0, ffma2(a1[2], v1, 0ULL));
                float2 f = unpack2(acc); s2 = f.x + f.y;
            }
            {
                u64 acc = ffma2(a0[3], v0, ffma2(a1[3], v1, 0ULL));
                float2 f = unpack2(acc); s3 = f.x + f.y;
            }
            s0 += __shfl_xor_sync(0xffffffffu, s2, 16);
            s1 += __shfl_xor_sync(0xffffffffu, s3, 16);
            s0 += __shfl_xor_sync(0xffffffffu, s1, 8);
            s0 += __shfl_xor_sync(0xffffffffu, s0, 4);
            s0 += __shfl_xor_sync(0xffffffffu, s0, 2);
            s0 += __shfl_xor_sync(0xffffffffu, s0, 1);
            pd[j] = s0;                     // full dot of row r0+q
        }
        // softmax over j for row r0+q (once per 4 rows; per-quarter data)
        float m01 = fmaxf(pd[0], pd[1]), m23 = fmaxf(pd[2], pd[3]);
        float m45 = fmaxf(pd[4], pd[5]), m67 = fmaxf(pd[6], pd[7]);
        float m89 = fmaxf(pd[8], pd[9]);
        float mx = fmaxf(fmaxf(fmaxf(m01, m23), fmaxf(m45, m67)), m89);
        float Z = 0.f;
#pragma unroll
        for (int j = 0; j < J_; j++) { pd[j] = __expf(pd[j] - mx); Z += pd[j]; }
        float rZ = __fdividef(1.0f, Z);
        // accumulate: coefficient for slot r = shfl_xor(c_own, 8r)
#pragma unroll
        for (int j = 0; j < J_; j++) {
            float c0 = pd[j] * rZ;                            // row q
            float c1 = __shfl_xor_sync(0xffffffffu, c0, 8);   // row q^1
            float c2 = __shfl_xor_sync(0xffffffffu, c0, 16);  // row q^2
            float c3 = __shfl_xor_sync(0xffffffffu, c0, 24);  // row q^3
            u64 cc;
            cc = pack2(c0, c0);
            p20[j] = ffma2(cc, a0[0], p20[j]);
            p21[j] = ffma2(cc, a1[0], p21[j]);
            cc = pack2(c1, c1);
            p20[j] = ffma2(cc, a0[1], p20[j]);
            p21[j] = ffma2(cc, a1[1], p21[j]);
            cc = pack2(c2, c2);
            p20[j] = ffma2(cc, a0[2], p20[j]);
            p21[j] = ffma2(cc, a1[2], p21[j]);
            cc = pack2(c3, c3);
            p20[j] = ffma2(cc, a0[3], p20[j]);
            p21[j] = ffma2(cc, a1[3], p21[j]);
        }
    }

    // aggregate the 8 warps via smem, then 1 coalesced gmem atomic pass
#pragma unroll
    for (int j = 0; j < J_; j++) {
        float2 a = unpack2(p20[j]);
        float2 c = unpack2(p21[j]);
        float* d = ps + j*K_ + lane*4;
        atomicAdd(d+0, a.x); atomicAdd(d+1, a.y);
        atomicAdd(d+2, c.x); atomicAdd(d+3, c.y);
    }
    __syncthreads();
    float* pb = p + b*J_*K_;
    for (int i = tid; i < J_*K_; i += 256)
        atomicAdd(pb + i, ps[i]);
}

// o2[b,j,d] = sum_k p2[b,j,k]*W[k,jd]; out = squash(o2) over d
__global__ void k_final(const float* __restrict__ W, float* __restrict__ out) {
    int b = blockIdx.x, t = threadIdx.x;   // 160 threads
    int j = t >> 4;
    __shared__ float so[F_];
    const float* pj = g_p2 + b*J_*K_ + j*K_;
    const float* wt = g_wt + t*K_;
    float acc = 0.f;
#pragma unroll 16
    for (int k = 0; k < K_; k++) acc += pj[k] * wt[k];
    so[t] = acc;
    __syncthreads();
    float s2 = 0.f;
#pragma unroll
    for (int d2 = 0; d2 < D_; d2++) { float x = so[j*D_ + d2]; s2 += x*x; }
    out[b*F_ + t] = acc * s2 / ((1.f + s2) * sqrtf(s2 + 1e-7f));
}

extern "C" void kernel_launch(void* const* d_in, const int* in_sizes, int n_in,
                              void* d_out, int out_size) {
    const float* u = (const float*)d_in[0];
    const float* W = (const float*)d_in[1];
    float* out = (float*)d_out;

    k_prep<<<320, 256>>>(W);             // zero scratch + transpose W
    k_sum<<<dim3(8, B_), 256>>>(u);
    k_ov<<<B_, 256>>>(W, 0);             // o0 (c uniform), v1
    k_pass<<<512, 256>>>(u, 0);          // b1 -> softmax -> p1
    k_ov<<<B_, 256>>>(W, 1);             // o1, v2
    k_pass<<<512, 256>>>(u, 1);          // b2 -> softmax -> p2
    k_final<<<B_, F_>>>(W, out);         // o2 -> squash
}

// round 11
// speedup vs baseline: 1.3159x; 1.0565x over previous
#include <cuda_runtime.h>
#include <math.h>

#define B_  64
#define N_  2048
#define K_  128
#define J_  10
#define D_  16
#define F_  160   // J_*D_

typedef unsigned long long u64;

// scratch (device globals: no allocation allowed)
__device__ float g_s [B_*K_];        // sum over n of u
__device__ float g_wt[F_*K_];        // W transposed: wt[f*128 + k] = W[k*160 + f]
__device__ float g_v [B_*J_*K_];     // v[b,j,k] = sum_d W[k,jd]*o[b,j,d]
__device__ float g_p1[B_*J_*K_];     // p after routing iter 1
__device__ float g_p2[B_*J_*K_];     // p after routing iter 2

__device__ __forceinline__ u64 ffma2(u64 a, u64 b, u64 c) {
    u64 d; asm("fma.rn.f32x2 %0, %1, %2, %3;" : "=l"(d) : "l"(a), "l"(b), "l"(c));
    return d;
}
__device__ __forceinline__ u64 pack2(float x, float y) {
    u64 d; asm("mov.b64 %0, {%1, %2};" : "=l"(d) : "f"(x), "f"(y));
    return d;
}
__device__ __forceinline__ float2 unpack2(u64 v) {
    float2 r; asm("mov.b64 {%0, %1}, %2;" : "=f"(r.x), "=f"(r.y) : "l"(v));
    return r;
}

// prep: zero scratch + transpose W (grid 320 x 256)
__global__ void k_prep(const float* __restrict__ W) {
    int i = blockIdx.x * blockDim.x + threadIdx.x;
    if (i < B_*K_) g_s[i] = 0.f;
    if (i < B_*J_*K_) { g_p1[i] = 0.f; g_p2[i] = 0.f; }
    if (i < F_*K_) {
        int f = i >> 7, k = i & 127;
        g_wt[i] = W[k*F_ + f];
    }
}

// s[b,k] = sum_n u[b,n,k]  (512 blocks; smem pre-reduce; 1 atomic per k per block)
__global__ void k_sum(const float* __restrict__ u) {
    int b = blockIdx.y;
    int chunk = blockIdx.x;            // 0..7, 256 rows each
    int k4 = threadIdx.x & 31;
    int rg = threadIdx.x >> 5;
    const float4* up = (const float4*)(u + ((size_t)b*N_ + (size_t)chunk*256 + (size_t)rg*32)*K_);
    float4 acc = make_float4(0.f,0.f,0.f,0.f);
#pragma unroll 8
    for (int r = 0; r < 32; r++) {
        float4 t = up[r*32 + k4];
        acc.x += t.x; acc.y += t.y; acc.z += t.z; acc.w += t.w;
    }
    __shared__ float4 sred[8][32];
    sred[rg][k4] = acc;
    __syncthreads();
    if (rg == 0) {
#pragma unroll
        for (int i = 1; i < 8; i++) {
            float4 t = sred[i][k4];
            acc.x += t.x; acc.y += t.y; acc.z += t.z; acc.w += t.w;
        }
        float* sp = g_s + b*K_ + k4*4;
        atomicAdd(sp+0, acc.x); atomicAdd(sp+1, acc.y);
        atomicAdd(sp+2, acc.z); atomicAdd(sp+3, acc.w);
    }
}

// mode 0: o[b,j,d] = 0.1 * sum_k s[b,k]   * W[k, j*16+d]
// mode 1: o[b,j,d] =       sum_k p1[b,j,k]* W[k, j*16+d]
// then    v[b,j,k] = sum_d o[b,j,d] * W[k, j*16+d]
// Phase A: one warp per output column f, coalesced LDG.128 from g_wt,
// 5-shfl butterfly -> latency-tolerant (20 f per warp, all independent).
__global__ void k_ov(const float* __restrict__ W, int mode) {
    int b = blockIdx.x, t = threadIdx.x;   // 256 threads, 8 warps
    int warp = t >> 5, lane = t & 31;
    __shared__ float src[J_*K_];
    __shared__ float so[F_];
    if (mode == 0) {
        if (t < K_) src[t] = g_s[b*K_ + t];
    } else {
        for (int i = t; i < J_*K_; i += 256) src[i] = g_p1[b*J_*K_ + i];
    }
    __syncthreads();

    // phase A: warp w computes f = w, w+8, ..., w+152
#pragma unroll
    for (int fi = 0; fi < 20; fi++) {
        int f = warp + fi*8;
        float4 w4 = ((const float4*)(g_wt + f*K_))[lane];
        const float* sp = (mode == 0) ? src : (src + (f >> 4)*K_);
        float4 s4 = ((const float4*)sp)[lane];
        u64 acc = ffma2(pack2(w4.x, w4.y), pack2(s4.x, s4.y),
                  ffma2(pack2(w4.z, w4.w), pack2(s4.z, s4.w), 0ULL));
        float2 fr = unpack2(acc);
        float d = fr.x + fr.y;
#pragma unroll
        for (int m = 16; m >= 1; m >>= 1)
            d += __shfl_xor_sync(0xffffffffu, d, m);
        if (lane == 0) so[f] = (mode == 0) ? 0.1f * d : d;
    }
    __syncthreads();

    // phase B: v[j,k] = sum_d o[j,d] * W[k, j*16+d]
#pragma unroll
    for (int e = t; e < J_*K_; e += 256) {
        int jj = e >> 7, k = e & 127;
        const float4* wrow = (const float4*)(W + k*F_ + jj*D_);
        const float4* oj = (const float4*)(so + jj*D_);
        float4 w0 = wrow[0], w1 = wrow[1], w2 = wrow[2], w3 = wrow[3];
        float4 o0 = oj[0], o1 = oj[1], o2 = oj[2], o3 = oj[3];
        float v = w0.x*o0.x + w0.y*o0.y + w0.z*o0.z + w0.w*o0.w
                + w1.x*o1.x + w1.y*o1.y + w1.z*o1.z + w1.w*o1.w
                + w2.x*o2.x + w2.y*o2.y + w2.z*o2.z + w2.w*o2.w
                + w3.x*o3.x + w3.y*o3.y + w3.z*o3.z + w3.w*o3.w;
        g_v[b*J_*K_ + e] = v;
    }
}

// fused pass: dots -> softmax -> p accumulation, 4 rows per warp-iteration.
// Lane owns k = 4*lane..4*lane+3; quarter q = lane>>3; slot r = row r0+(q^r).
// v in REGISTERS (R8-proven faster than smem: no LDS in the j-loop chain).
__global__ void __launch_bounds__(256, 2)
k_pass(const float* __restrict__ u, int which) {
    float* p = (which == 0) ? g_p1 : g_p2;
    int b = blockIdx.x >> 3;
    int seg = blockIdx.x & 7;              // 256 rows per block
    int tid = threadIdx.x;
    int warp = tid >> 5, lane = tid & 31;
    int q = lane >> 3;

    __shared__ float ps[J_*K_];
    for (int i = tid; i < J_*K_; i += 256) ps[i] = 0.f;

    // v[j] slice for this lane (k = 4*lane..4*lane+3), kept in registers
    u64 v0[J_], v1[J_];
    {
        const float4* vb = (const float4*)(g_v + b*J_*K_);
#pragma unroll
        for (int j = 0; j < J_; j++) {
            float4 t = vb[j*32 + lane];
            v0[j] = pack2(t.x, t.y);
            v1[j] = pack2(t.z, t.w);
        }
    }
    __syncthreads();

    u64 p20[J_], p21[J_];
#pragma unroll
    for (int j = 0; j < J_; j++) { p20[j] = 0ULL; p21[j] = 0ULL; }

    const float4* ub = (const float4*)(u + ((size_t)b*N_ + (size_t)seg*256)*K_);

#pragma unroll 1
    for (int it = 0; it < 8; it++) {
        int r0 = warp*32 + it*4;
        // q-relative row loads: slot r holds row r0 + (q^r) at this lane's k
        u64 a0[4], a1[4];
#pragma unroll
        for (int r = 0; r < 4; r++) {
            float4 t = ub[(size_t)(r0 + (q ^ r))*32 + lane];
            a0[r] = pack2(t.x, t.y);
            a1[r] = pack2(t.z, t.w);
        }

        // dots + select-free split reduction
        float pd[J_];
#pragma unroll
        for (int j = 0; j < J_; j++) {
            float s0, s1, s2, s3;
            {
                u64 acc = ffma2(a0[0], v0[j], ffma2(a1[0], v1[j], 0ULL));
                float2 f = unpack2(acc); s0 = f.x + f.y;
            }
            {
                u64 acc = ffma2(a0[1], v0[j], ffma2(a1[1], v1[j], 0ULL));
                float2 f = unpack2(acc); s1 = f.x + f.y;
            }
            {
                u64 acc = ffma2(a0[2], v0[j], ffma2(a1[2], v1[j], 0ULL));
                float2 f = unpack2(acc); s2 = f.x + f.y;
            }
            {
                u64 acc = ffma2(a0[3], v0[j], ffma2(a1[3], v1[j], 0ULL));
                float2 f = unpack2(acc); s3 = f.x + f.y;
            }
            s0 += __shfl_xor_sync(0xffffffffu, s2, 16);
            s1 += __shfl_xor_sync(0xffffffffu, s3, 16);
            s0 += __shfl_xor_sync(0xffffffffu, s1, 8);
            s0 += __shfl_xor_sync(0xffffffffu, s0, 4);
            s0 += __shfl_xor_sync(0xffffffffu, s0, 2);
            s0 += __shfl_xor_sync(0xffffffffu, s0, 1);
            pd[j] = s0;                     // full dot of row r0+q
        }
        // softmax over j for row r0+q (once per 4 rows; per-quarter data)
        float m01 = fmaxf(pd[0], pd[1]), m23 = fmaxf(pd[2], pd[3]);
        float m45 = fmaxf(pd[4], pd[5]), m67 = fmaxf(pd[6], pd[7]);
        float m89 = fmaxf(pd[8], pd[9]);
        float mx = fmaxf(fmaxf(fmaxf(m01, m23), fmaxf(m45, m67)), m89);
        float Z = 0.f;
#pragma unroll
        for (int j = 0; j < J_; j++) { pd[j] = __expf(pd[j] - mx); Z += pd[j]; }
        float rZ = __fdividef(1.0f, Z);
        // accumulate: coefficient for slot r = shfl_xor(c_own, 8r)
#pragma unroll
        for (int j = 0; j < J_; j++) {
            float c0 = pd[j] * rZ;                            // row q
            float c1 = __shfl_xor_sync(0xffffffffu, c0, 8);   // row q^1
            float c2 = __shfl_xor_sync(0xffffffffu, c0, 16);  // row q^2
            float c3 = __shfl_xor_sync(0xffffffffu, c0, 24);  // row q^3
            u64 cc;
            cc = pack2(c0, c0);
            p20[j] = ffma2(cc, a0[0], p20[j]);
            p21[j] = ffma2(cc, a1[0], p21[j]);
            cc = pack2(c1, c1);
            p20[j] = ffma2(cc, a0[1], p20[j]);
            p21[j] = ffma2(cc, a1[1], p21[j]);
            cc = pack2(c2, c2);
            p20[j] = ffma2(cc, a0[2], p20[j]);
            p21[j] = ffma2(cc, a1[2], p21[j]);
            cc = pack2(c3, c3);
            p20[j] = ffma2(cc, a0[3], p20[j]);
            p21[j] = ffma2(cc, a1[3], p21[j]);
        }
    }

    // aggregate the 8 warps via smem, then 1 coalesced gmem atomic pass
#pragma unroll
    for (int j = 0; j < J_; j++) {
        float2 a = unpack2(p20[j]);
        float2 c = unpack2(p21[j]);
        float* d = ps + j*K_ + lane*4;
        atomicAdd(d+0, a.x); atomicAdd(d+1, a.y);
        atomicAdd(d+2, c.x); atomicAdd(d+3, c.y);
    }
    __syncthreads();
    float* pb = p + b*J_*K_;
    for (int i = tid; i < J_*K_; i += 256)
        atomicAdd(pb + i, ps[i]);
}

// o2[b,j,d] = sum_k p2[b,j,k]*W[k,jd]; out = squash(o2) over d
__global__ void k_final(const float* __restrict__ W, float* __restrict__ out) {
    int b = blockIdx.x, t = threadIdx.x;   // 160 threads
    int j = t >> 4;
    __shared__ float so[F_];
    const float* pj = g_p2 + b*J_*K_ + j*K_;
    const float* wt = g_wt + t*K_;
    float acc = 0.f;
#pragma unroll 16
    for (int k = 0; k < K_; k++) acc += pj[k] * wt[k];
    so[t] = acc;
    __syncthreads();
    float s2 = 0.f;
#pragma unroll
    for (int d2 = 0; d2 < D_; d2++) { float x = so[j*D_ + d2]; s2 += x*x; }
    out[b*F_ + t] = acc * s2 / ((1.f + s2) * sqrtf(s2 + 1e-7f));
}

extern "C" void kernel_launch(void* const* d_in, const int* in_sizes, int n_in,
                              void* d_out, int out_size) {
    const float* u = (const float*)d_in[0];
    const float* W = (const float*)d_in[1];
    float* out = (float*)d_out;

    k_prep<<<320, 256>>>(W);             // zero scratch + transpose W
    k_sum<<<dim3(8, B_), 256>>>(u);
    k_ov<<<B_, 256>>>(W, 0);             // o0 (c uniform), v1
    k_pass<<<512, 256>>>(u, 0);          // b1 -> softmax -> p1
    k_ov<<<B_, 256>>>(W, 1);             // o1, v2
    k_pass<<<512, 256>>>(u, 1);          // b2 -> softmax -> p2
    k_final<<<B_, F_>>>(W, out);         // o2 -> squash
}

// round 12
// speedup vs baseline: 1.3634x; 1.0361x over previous
#include <cuda_runtime.h>
#include <math.h>

#define B_  64
#define N_  2048
#define K_  128
#define J_  10
#define D_  16
#define F_  160   // J_*D_

typedef unsigned long long u64;

// scratch (device globals: no allocation allowed)
__device__ float g_s [B_*K_];        // sum over n of u
__device__ float g_wt[F_*K_];        // W transposed: wt[f*128 + k] = W[k*160 + f]
__device__ float g_v [B_*J_*K_];     // v[b,j,k] = sum_d W[k,jd]*o[b,j,d]
__device__ float g_p1[B_*J_*K_];     // p after routing iter 1
__device__ float g_p2[B_*J_*K_];     // p after routing iter 2

__device__ __forceinline__ u64 ffma2(u64 a, u64 b, u64 c) {
    u64 d; asm("fma.rn.f32x2 %0, %1, %2, %3;" : "=l"(d) : "l"(a), "l"(b), "l"(c));
    return d;
}
__device__ __forceinline__ u64 pack2(float x, float y) {
    u64 d; asm("mov.b64 %0, {%1, %2};" : "=l"(d) : "f"(x), "f"(y));
    return d;
}
__device__ __forceinline__ float2 unpack2(u64 v) {
    float2 r; asm("mov.b64 {%0, %1}, %2;" : "=f"(r.x), "=f"(r.y) : "l"(v));
    return r;
}

// prep: zero scratch + transpose W (grid 320 x 256)
__global__ void k_prep(const float* __restrict__ W) {
    int i = blockIdx.x * blockDim.x + threadIdx.x;
    if (i < B_*K_) g_s[i] = 0.f;
    if (i < B_*J_*K_) { g_p1[i] = 0.f; g_p2[i] = 0.f; }
    if (i < F_*K_) {
        int f = i >> 7, k = i & 127;
        g_wt[i] = W[k*F_ + f];
    }
}

// s[b,k] = sum_n u[b,n,k]  (512 blocks; smem pre-reduce; 1 atomic per k per block)
__global__ void k_sum(const float* __restrict__ u) {
    int b = blockIdx.y;
    int chunk = blockIdx.x;            // 0..7, 256 rows each
    int k4 = threadIdx.x & 31;
    int rg = threadIdx.x >> 5;
    const float4* up = (const float4*)(u + ((size_t)b*N_ + (size_t)chunk*256 + (size_t)rg*32)*K_);
    float4 acc = make_float4(0.f,0.f,0.f,0.f);
#pragma unroll 8
    for (int r = 0; r < 32; r++) {
        float4 t = up[r*32 + k4];
        acc.x += t.x; acc.y += t.y; acc.z += t.z; acc.w += t.w;
    }
    __shared__ float4 sred[8][32];
    sred[rg][k4] = acc;
    __syncthreads();
    if (rg == 0) {
#pragma unroll
        for (int i = 1; i < 8; i++) {
            float4 t = sred[i][k4];
            acc.x += t.x; acc.y += t.y; acc.z += t.z; acc.w += t.w;
        }
        float* sp = g_s + b*K_ + k4*4;
        atomicAdd(sp+0, acc.x); atomicAdd(sp+1, acc.y);
        atomicAdd(sp+2, acc.z); atomicAdd(sp+3, acc.w);
    }
}

// mode 0: o[b,j,d] = 0.1 * sum_k s[b,k]   * W[k, j*16+d]
// mode 1: o[b,j,d] =       sum_k p1[b,j,k]* W[k, j*16+d]
// then    v[b,j,k] = sum_d o[b,j,d] * W[k, j*16+d]
__global__ void k_ov(const float* __restrict__ W, int mode) {
    int b = blockIdx.x, t = threadIdx.x;   // 256 threads, 8 warps
    int warp = t >> 5, lane = t & 31;
    __shared__ float src[J_*K_];
    __shared__ float so[F_];
    if (mode == 0) {
        if (t < K_) src[t] = g_s[b*K_ + t];
    } else {
        for (int i = t; i < J_*K_; i += 256) src[i] = g_p1[b*J_*K_ + i];
    }
    __syncthreads();

    // phase A: warp w computes f = w, w+8, ..., w+152
#pragma unroll
    for (int fi = 0; fi < 20; fi++) {
        int f = warp + fi*8;
        float4 w4 = ((const float4*)(g_wt + f*K_))[lane];
        const float* sp = (mode == 0) ? src : (src + (f >> 4)*K_);
        float4 s4 = ((const float4*)sp)[lane];
        u64 acc = ffma2(pack2(w4.x, w4.y), pack2(s4.x, s4.y),
                  ffma2(pack2(w4.z, w4.w), pack2(s4.z, s4.w), 0ULL));
        float2 fr = unpack2(acc);
        float d = fr.x + fr.y;
#pragma unroll
        for (int m = 16; m >= 1; m >>= 1)
            d += __shfl_xor_sync(0xffffffffu, d, m);
        if (lane == 0) so[f] = (mode == 0) ? 0.1f * d : d;
    }
    __syncthreads();

    // phase B: v[j,k] = sum_d o[j,d] * W[k, j*16+d]
#pragma unroll
    for (int e = t; e < J_*K_; e += 256) {
        int jj = e >> 7, k = e & 127;
        const float4* wrow = (const float4*)(W + k*F_ + jj*D_);
        const float4* oj = (const float4*)(so + jj*D_);
        float4 w0 = wrow[0], w1 = wrow[1], w2 = wrow[2], w3 = wrow[3];
        float4 o0 = oj[0], o1 = oj[1], o2 = oj[2], o3 = oj[3];
        float v = w0.x*o0.x + w0.y*o0.y + w0.z*o0.z + w0.w*o0.w
                + w1.x*o1.x + w1.y*o1.y + w1.z*o1.z + w1.w*o1.w
                + w2.x*o2.x + w2.y*o2.y + w2.z*o2.z + w2.w*o2.w
                + w3.x*o3.x + w3.y*o3.y + w3.z*o3.z + w3.w*o3.w;
        g_v[b*J_*K_ + e] = v;
    }
}

// fused pass: dots -> softmax -> p accumulation, 8 rows per warp-iteration.
// Lane owns k = 4*lane..4*lane+3; oct o = lane>>2 owns row r0+o.
// Slot r loaded from row r0+(o^r). Cross-oct fold (masks 16/8/4 pair slots
// r^4 / r^2 / r^1), 2 in-oct levels -> 9 shfl per j per 8 rows. Softmax runs
// ONCE per 8 rows. Coefficient for slot r = shfl_xor(c_own, r<<2).
// v in smem: only 1 LDS.128 per j per 8 rows (u slots need the registers).
__global__ void __launch_bounds__(256, 2)
k_pass(const float* __restrict__ u, int which) {
    float* p = (which == 0) ? g_p1 : g_p2;
    int b = blockIdx.x >> 3;
    int seg = blockIdx.x & 7;              // 256 rows per block
    int tid = threadIdx.x;
    int warp = tid >> 5, lane = tid & 31;
    int oct = lane >> 2;

    __shared__ float sv[J_*K_];
    __shared__ float ps[J_*K_];
    {
        const float* vb = g_v + b*J_*K_;
        for (int i = tid; i < J_*K_; i += 256) { sv[i] = vb[i]; ps[i] = 0.f; }
    }
    __syncthreads();

    u64 p20[J_], p21[J_];
#pragma unroll
    for (int j = 0; j < J_; j++) { p20[j] = 0ULL; p21[j] = 0ULL; }

    const float4* ub = (const float4*)(u + ((size_t)b*N_ + (size_t)seg*256)*K_);
    const float4* svl = ((const float4*)sv) + lane;   // sv[j*K_ + 4*lane]

#pragma unroll 1
    for (int it = 0; it < 4; it++) {
        int r0 = warp*32 + it*8;
        // oct-relative row loads: slot r = row r0 + (oct^r) at this lane's k
        u64 a0[8], a1[8];
#pragma unroll
        for (int r = 0; r < 8; r++) {
            float4 t = ub[(r0 + (oct ^ r))*32 + lane];
            a0[r] = pack2(t.x, t.y);
            a1[r] = pack2(t.z, t.w);
        }

        // dots + select-free cross-oct fold
        float pd[J_];
#pragma unroll
        for (int j = 0; j < J_; j++) {
            float4 vv = svl[j*32];         // conflict-free LDS.128
            u64 v0 = pack2(vv.x, vv.y);
            u64 v1 = pack2(vv.z, vv.w);
            float s[8];
#pragma unroll
            for (int r = 0; r < 8; r++) {
                u64 acc = ffma2(a0[r], v0, ffma2(a1[r], v1, 0ULL));
                float2 f = unpack2(acc);
                s[r] = f.x + f.y;
            }
            s[0] += __shfl_xor_sync(0xffffffffu, s[4], 16);
            s[1] += __shfl_xor_sync(0xffffffffu, s[5], 16);
            s[2] += __shfl_xor_sync(0xffffffffu, s[6], 16);
            s[3] += __shfl_xor_sync(0xffffffffu, s[7], 16);
            s[0] += __shfl_xor_sync(0xffffffffu, s[2], 8);
            s[1] += __shfl_xor_sync(0xffffffffu, s[3], 8);
            s[0] += __shfl_xor_sync(0xffffffffu, s[1], 4);
            s[0] += __shfl_xor_sync(0xffffffffu, s[0], 2);
            s[0] += __shfl_xor_sync(0xffffffffu, s[0], 1);
            pd[j] = s[0];                   // full dot of row r0+oct
        }
        // softmax over j for row r0+oct (ONCE per 8 rows)
        float m01 = fmaxf(pd[0], pd[1]), m23 = fmaxf(pd[2], pd[3]);
        float m45 = fmaxf(pd[4], pd[5]), m67 = fmaxf(pd[6], pd[7]);
        float m89 = fmaxf(pd[8], pd[9]);
        float mx = fmaxf(fmaxf(fmaxf(m01, m23), fmaxf(m45, m67)), m89);
        float Z = 0.f;
#pragma unroll
        for (int j = 0; j < J_; j++) { pd[j] = __expf(pd[j] - mx); Z += pd[j]; }
        float rZ = __fdividef(1.0f, Z);
        // accumulate: coefficient for slot r = shfl_xor(c_own, r<<2)
#pragma unroll
        for (int j = 0; j < J_; j++) {
            float c0 = pd[j] * rZ;          // row r0+oct
            u64 cc = pack2(c0, c0);
            p20[j] = ffma2(cc, a0[0], p20[j]);
            p21[j] = ffma2(cc, a1[0], p21[j]);
#pragma unroll
            for (int r = 1; r < 8; r++) {
                float cr = __shfl_xor_sync(0xffffffffu, c0, r << 2);
                cc = pack2(cr, cr);
                p20[j] = ffma2(cc, a0[r], p20[j]);
                p21[j] = ffma2(cc, a1[r], p21[j]);
            }
        }
    }

    // aggregate the 8 warps via smem, then 1 coalesced gmem atomic pass
#pragma unroll
    for (int j = 0; j < J_; j++) {
        float2 a = unpack2(p20[j]);
        float2 c = unpack2(p21[j]);
        float* d = ps + j*K_ + lane*4;
        atomicAdd(d+0, a.x); atomicAdd(d+1, a.y);
        atomicAdd(d+2, c.x); atomicAdd(d+3, c.y);
    }
    __syncthreads();
    float* pb = p + b*J_*K_;
    for (int i = tid; i < J_*K_; i += 256)
        atomicAdd(pb + i, ps[i]);
}

// o2[b,j,d] = sum_k p2[b,j,k]*W[k,jd]; out = squash(o2) over d
__global__ void k_final(const float* __restrict__ W, float* __restrict__ out) {
    int b = blockIdx.x, t = threadIdx.x;   // 160 threads
    int j = t >> 4;
    __shared__ float so[F_];
    const float* pj = g_p2 + b*J_*K_ + j*K_;
    const float* wt = g_wt + t*K_;
    float acc = 0.f;
#pragma unroll 16
    for (int k = 0; k < K_; k++) acc += pj[k] * wt[k];
    so[t] = acc;
    __syncthreads();
    float s2 = 0.f;
#pragma unroll
    for (int d2 = 0; d2 < D_; d2++) { float x = so[j*D_ + d2]; s2 += x*x; }
    out[b*F_ + t] = acc * s2 / ((1.f + s2) * sqrtf(s2 + 1e-7f));
}

extern "C" void kernel_launch(void* const* d_in, const int* in_sizes, int n_in,
                              void* d_out, int out_size) {
    const float* u = (const float*)d_in[0];
    const float* W = (const float*)d_in[1];
    float* out = (float*)d_out;

    k_prep<<<320, 256>>>(W);             // zero scratch + transpose W
    k_sum<<<dim3(8, B_), 256>>>(u);
    k_ov<<<B_, 256>>>(W, 0);             // o0 (c uniform), v1
    k_pass<<<512, 256>>>(u, 0);          // b1 -> softmax -> p1
    k_ov<<<B_, 256>>>(W, 1);             // o1, v2
    k_pass<<<512, 256>>>(u, 1);          // b2 -> softmax -> p2
    k_final<<<B_, F_>>>(W, out);         // o2 -> squash
}